// round 16
// baseline (speedup 1.0000x reference)
#include <cuda_runtime.h>
#include <cuda_bf16.h>
#include <math.h>

#define NR   32768
#define DIM  512
#define KCODE 8192
#define DECAY 0.99f
#define ONE_MINUS_DECAY 0.01f
#define EPS 1e-5f
#define MARGIN 3.0e-3f
#define MAXCAND 192
#define NSPLIT 4
#define CODES_PER_UNIT (KCODE / NSPLIT)   // 2048

// ---------------- scratch (__device__ globals; no allocation) ----------------
static __device__ __align__(256) float  g_flat[NR * DIM];      // normalized inputs fp32
static __device__ __align__(256) float  g_embn[KCODE * DIM];   // normalized embedding fp32
static __device__ __align__(256) __nv_bfloat16 g_flat_hi[NR * DIM];
static __device__ __align__(256) __nv_bfloat16 g_emb_hi[KCODE * DIM];
static __device__ int    g_clist[NR * MAXCAND];
static __device__ int    g_ccnt[NR];
static __device__ float  g_counts[KCODE];
static __device__ __align__(256) float  g_dw[KCODE * DIM];
static __device__ double g_loss;
static __device__ float  g_newcs[KCODE];

// ---------------- output layout (float32, concatenated in return order) -----
#define OFF_LOSS 16777216
#define OFF_IDX  16777217
#define OFF_CS   16809985
#define OFF_W    16818177
#define OFF_EMB  21012481

// ---------------- SMEM layout for argmax kernel ----------------
// A:    128 rows x 512 bf16 swizzled               [0, 131072)
// B:    3 ring bufs x (256 codes x 64 bf16)        [131072, 229376)
// PM:   128 rows x 4 warps fp32                    [229376, 231424)
// RMAX: 128 fp32                                   [231424, 231936)
#define S_A 0
#define S_B 131072
#define S_PM 229376
#define S_RMAX 231424
#define SMEM_SZ 231936

__device__ __forceinline__ unsigned smem_u32(const void* p) {
    unsigned a;
    asm("{ .reg .u64 t; cvta.to.shared.u64 t, %1; cvt.u32.u64 %0, t; }" : "=r"(a) : "l"(p));
    return a;
}
__device__ __forceinline__ void cp16(unsigned dst, const void* src) {
    asm volatile("cp.async.cg.shared.global [%0], [%1], 16;" :: "r"(dst), "l"(src));
}
#define CP_COMMIT() asm volatile("cp.async.commit_group;" ::: "memory")
#define CP_WAIT1()  asm volatile("cp.async.wait_group 1;" ::: "memory")

__device__ __forceinline__ void ldsm4(unsigned addr, unsigned& r0, unsigned& r1,
                                      unsigned& r2, unsigned& r3) {
    asm volatile("ldmatrix.sync.aligned.m8n8.x4.shared.b16 {%0,%1,%2,%3}, [%4];"
                 : "=r"(r0), "=r"(r1), "=r"(r2), "=r"(r3) : "r"(addr));
}
__device__ __forceinline__ void mma16816(float* d, const unsigned* a,
                                         unsigned b0, unsigned b1) {
    asm volatile("mma.sync.aligned.m16n8k16.row.col.f32.bf16.bf16.f32 "
                 "{%0,%1,%2,%3}, {%4,%5,%6,%7}, {%8,%9}, {%0,%1,%2,%3};"
                 : "+f"(d[0]), "+f"(d[1]), "+f"(d[2]), "+f"(d[3])
                 : "r"(a[0]), "r"(a[1]), "r"(a[2]), "r"(a[3]), "r"(b0), "r"(b1));
}

// swizzled byte offsets
__device__ __forceinline__ unsigned aoff(int row, int c) {   // A: 64 x 16B chunks/row
    return (unsigned)row * 1024u + (unsigned)((c & 56) | ((c ^ row) & 7)) * 16u;
}
__device__ __forceinline__ unsigned boff(int n, int cl) {    // B: 8 x 16B chunks/row
    return (unsigned)n * 128u + (unsigned)((cl ^ n) & 7) * 16u;
}

// ---------------- kernels ----------------
__global__ void k_zero() {
    int i = blockIdx.x * blockDim.x + threadIdx.x;
    int stride = gridDim.x * blockDim.x;
    float4 z = make_float4(0.f, 0.f, 0.f, 0.f);
    int tot4 = KCODE * DIM / 4;
    for (int j = i; j < tot4; j += stride) ((float4*)g_dw)[j] = z;
    for (int j = i; j < KCODE; j += stride) g_counts[j] = 0.f;
    for (int j = i; j < NR; j += stride) g_ccnt[j] = 0;
    if (i == 0) g_loss = 0.0;
}

// normalize rows; emit fp32 + bf16-hi
__global__ void k_norm(const float* __restrict__ src, int which) {
    int row = blockIdx.x;
    int t = threadIdx.x;  // 128 threads, 4 floats each
    const float4* s = (const float4*)(src + (size_t)row * DIM);
    float4 v = s[t];
    float ss = v.x * v.x + v.y * v.y + v.z * v.z + v.w * v.w;
    #pragma unroll
    for (int o = 16; o; o >>= 1) ss += __shfl_xor_sync(0xFFFFFFFFu, ss, o);
    __shared__ float wsum[4];
    if ((t & 31) == 0) wsum[t >> 5] = ss;
    __syncthreads();
    float tot = wsum[0] + wsum[1] + wsum[2] + wsum[3];
    float inv = 1.0f / fmaxf(sqrtf(tot), 1e-12f);
    float4 o4 = make_float4(v.x * inv, v.y * inv, v.z * inv, v.w * inv);
    float* dst = which ? g_embn : g_flat;
    __nv_bfloat16* dhi = which ? g_emb_hi : g_flat_hi;
    ((float4*)(dst + (size_t)row * DIM))[t] = o4;
    __nv_bfloat162 h0, h1;
    h0.x = __float2bfloat16(o4.x); h0.y = __float2bfloat16(o4.y);
    h1.x = __float2bfloat16(o4.z); h1.y = __float2bfloat16(o4.w);
    ((__nv_bfloat162*)(dhi + (size_t)row * DIM))[2 * t]     = h0;
    ((__nv_bfloat162*)(dhi + (size_t)row * DIM))[2 * t + 1] = h1;
}

// prefetch B tile tt (256 codes x 64 dims) of this unit into ring buffer tt%3
__device__ __forceinline__ void prefetchB(unsigned sb, int tid, int tt, int code0) {
    const int nn = tt >> 3, nk = tt & 7;
    unsigned bb = sb + S_B + (unsigned)(tt % 3) * 32768u;
    #pragma unroll
    for (int p = 0; p < 8; p++) {
        int g = p * 256 + tid;
        int n = g >> 3, cl = g & 7;
        cp16(bb + boff(n, cl),
             g_emb_hi + (size_t)(code0 + nn * 256 + n) * DIM + nk * 64 + cl * 8);
    }
}

// HMMA GEMM-argmax: grid = (NR/128)*NSPLIT units; unit = (row-block, n-quarter).
// 8 warps = 2m x 4n of 64x64 tiles, CTA chunk 128x256, 3-stage cp.async ring,
// register epilogue, unit-local margin candidate collection (union is rescored
// exactly, so local margins preserve the global argmin).
__global__ __launch_bounds__(256, 1) void k_argmax_mma() {
    extern __shared__ __align__(16) char smem[];
    const unsigned sb = smem_u32(smem);
    float* pm   = (float*)(smem + S_PM);
    float* rmax = (float*)(smem + S_RMAX);
    const int tid = threadIdx.x;
    const int lane = tid & 31;
    const int wid = tid >> 5;
    const int rb = blockIdx.x >> 2;          // row-block
    const int nq = blockIdx.x & 3;           // n-quarter
    const int r0 = rb * 128;
    const int code0 = nq * CODES_PER_UNIT;

    const int mw = wid & 1;              // m-half (64 rows)
    const int nw = wid >> 1;             // n-quarter within chunk (64 cols)
    const int rA0 = mw * 64 + (lane & 15);
    const int cc  = lane >> 4;           // 16B-chunk half for ldsm
    const int nB0 = nw * 64 + (lane & 15);

    // ---- load resident A_hi (swizzled): 8192 chunks, 32/thread ----
    #pragma unroll 4
    for (int p = 0; p < 32; p++) {
        int g = p * 256 + tid;
        int row = g >> 6, c = g & 63;
        uint4 v = *(const uint4*)(g_flat_hi + (size_t)(r0 + row) * DIM + c * 8);
        *(uint4*)(smem + S_A + aoff(row, c)) = v;
    }
    if (tid < 128) rmax[tid] = -1e30f;

    float acc[4][8][4];
    #pragma unroll
    for (int mi = 0; mi < 4; mi++)
        #pragma unroll
        for (int nj = 0; nj < 8; nj++)
            #pragma unroll
            for (int q = 0; q < 4; q++) acc[mi][nj][q] = 0.f;

    // ---- prefetch tiles 0, 1 ----
    prefetchB(sb, tid, 0, code0); CP_COMMIT();
    prefetchB(sb, tid, 1, code0); CP_COMMIT();

    const int NT = (CODES_PER_UNIT / 256) * 8;   // 64 tiles
    for (int t = 0; t < NT; t++) {
        CP_WAIT1();               // tile t arrived (this thread's copies)
        __syncthreads();          // tile t visible; buf (t+2)%3 free; A visible (t=0)
        if (t + 2 < NT) prefetchB(sb, tid, t + 2, code0);
        CP_COMMIT();

        const unsigned Bb = sb + S_B + (unsigned)(t % 3) * 32768u;
        const int nk = t & 7;
        #pragma unroll
        for (int ks = 0; ks < 4; ks++) {
            const int cA = nk * 8 + ks * 2 + cc;
            unsigned a[4][4];
            #pragma unroll
            for (int mi = 0; mi < 4; mi++)
                ldsm4(sb + S_A + aoff(rA0 + mi * 16, cA),
                      a[mi][0], a[mi][1], a[mi][2], a[mi][3]);
            unsigned b[4][4];
            #pragma unroll
            for (int j = 0; j < 4; j++)
                ldsm4(Bb + boff(nB0 + j * 16, ks * 2 + cc),
                      b[j][0], b[j][1], b[j][2], b[j][3]);
            #pragma unroll
            for (int mi = 0; mi < 4; mi++)
                #pragma unroll
                for (int nj = 0; nj < 8; nj++) {
                    int jj = nj >> 1, s = nj & 1;
                    mma16816(acc[mi][nj], a[mi], b[jj][s], b[jj][s + 2]);
                }
        }

        if (nk == 7) {
            const int nc = t >> 3;
            // ---- register epilogue: per-row max over this warp's 64 cols ----
            float rm[8];
            #pragma unroll
            for (int mi = 0; mi < 4; mi++)
                #pragma unroll
                for (int h = 0; h < 2; h++) {
                    float m = -1e30f;
                    #pragma unroll
                    for (int nj = 0; nj < 8; nj++)
                        m = fmaxf(m, fmaxf(acc[mi][nj][h * 2], acc[mi][nj][h * 2 + 1]));
                    rm[mi * 2 + h] = m;
                }
            #pragma unroll
            for (int i = 0; i < 8; i++) {
                rm[i] = fmaxf(rm[i], __shfl_xor_sync(0xFFFFFFFFu, rm[i], 1));
                rm[i] = fmaxf(rm[i], __shfl_xor_sync(0xFFFFFFFFu, rm[i], 2));
            }
            if ((lane & 3) == 0) {
                #pragma unroll
                for (int mi = 0; mi < 4; mi++)
                    #pragma unroll
                    for (int h = 0; h < 2; h++) {
                        int row = mw * 64 + mi * 16 + h * 8 + (lane >> 2);
                        pm[row * 4 + nw] = rm[mi * 2 + h];
                    }
            }
            __syncthreads();
            if (tid < 128) {
                float4 v = *(float4*)&pm[tid * 4];
                float cm = fmaxf(fmaxf(v.x, v.y), fmaxf(v.z, v.w));
                float nm = fmaxf(rmax[tid], cm);
                rmax[tid] = nm;
                pm[tid * 4] = nm - MARGIN;     // unit-local threshold
            }
            __syncthreads();
            // ---- candidate extraction (rare) ----
            #pragma unroll
            for (int mi = 0; mi < 4; mi++)
                #pragma unroll
                for (int h = 0; h < 2; h++) {
                    int row = mw * 64 + mi * 16 + h * 8 + (lane >> 2);
                    float th = pm[row * 4];
                    if (rm[mi * 2 + h] >= th) {
                        #pragma unroll
                        for (int nj = 0; nj < 8; nj++)
                            #pragma unroll
                            for (int q = 0; q < 2; q++) {
                                float v = acc[mi][nj][h * 2 + q];
                                if (v >= th) {
                                    int col = code0 + nc * 256 + nw * 64 + nj * 8 + (lane & 3) * 2 + q;
                                    int pos = atomicAdd(&g_ccnt[r0 + row], 1);
                                    if (pos < MAXCAND)
                                        g_clist[(size_t)(r0 + row) * MAXCAND + pos] = col;
                                }
                            }
                    }
                }
            // reset accumulators
            #pragma unroll
            for (int mi = 0; mi < 4; mi++)
                #pragma unroll
                for (int nj = 0; nj < 8; nj++)
                    #pragma unroll
                    for (int q = 0; q < 4; q++) acc[mi][nj][q] = 0.f;
        }
    }
}

// fused: exact fp32 rescore of candidates, then quantize/loss/counts/dw scatter.
// Overflowed candidate list (never expected) -> exact full scan fallback.
__global__ void k_rescore_quant(const float* __restrict__ x,
                                float* __restrict__ qout,
                                float* __restrict__ idx_out) {
    int row = blockIdx.x;
    int t = threadIdx.x;  // 128
    int cnt = g_ccnt[row];
    bool full = (cnt > MAXCAND);
    int total = full ? KCODE : cnt;
    __shared__ float sred[4];
    __shared__ float bestd;
    __shared__ int   besti;
    if (t == 0) { bestd = 1e30f; besti = 0x7FFFFFFF; }
    __syncthreads();
    float4 fv = ((const float4*)(g_flat + (size_t)row * DIM))[t];
    for (int c = 0; c < total; c++) {
        int idx = full ? c : g_clist[(size_t)row * MAXCAND + c];
        float4 e = ((const float4*)(g_embn + (size_t)idx * DIM))[t];
        float d = fv.x * e.x + fv.y * e.y + fv.z * e.z + fv.w * e.w;
        #pragma unroll
        for (int o = 16; o; o >>= 1) d += __shfl_xor_sync(0xFFFFFFFFu, d, o);
        if ((t & 31) == 0) sred[t >> 5] = d;
        __syncthreads();
        if (t == 0) {
            float dot = sred[0] + sred[1] + sred[2] + sred[3];
            float dist = 1.0f - dot;
            if (dist < bestd || (dist == bestd && idx < besti)) { bestd = dist; besti = idx; }
        }
        __syncthreads();
    }
    int idx = besti;
    if (t == 0) idx_out[row] = (float)idx;

    // ---- quant part ----
    float4 xv = ((const float4*)(x + (size_t)row * DIM))[t];
    float4 ev = ((const float4*)(g_embn + (size_t)idx * DIM))[t];
    float4 q; float d, s = 0.f;
    d = ev.x - xv.x; q.x = xv.x + d; s += d * d;
    d = ev.y - xv.y; q.y = xv.y + d; s += d * d;
    d = ev.z - xv.z; q.z = xv.z + d; s += d * d;
    d = ev.w - xv.w; q.w = xv.w + d; s += d * d;
    ((float4*)(qout + (size_t)row * DIM))[t] = q;

    float* dwp = g_dw + (size_t)idx * DIM + t * 4;
    atomicAdd(dwp + 0, fv.x);
    atomicAdd(dwp + 1, fv.y);
    atomicAdd(dwp + 2, fv.z);
    atomicAdd(dwp + 3, fv.w);

    #pragma unroll
    for (int o = 16; o; o >>= 1) s += __shfl_xor_sync(0xFFFFFFFFu, s, o);
    if ((t & 31) == 0) sred[t >> 5] = s;
    __syncthreads();
    if (t == 0) {
        atomicAdd(&g_loss, (double)(sred[0] + sred[1] + sred[2] + sred[3]));
        atomicAdd(&g_counts[idx], 1.0f);
    }
}

__global__ void k_cs(const float* __restrict__ ema_cs,
                     float* __restrict__ out_cs, float* __restrict__ out_loss) {
    int t = threadIdx.x;
    float pre[8];
    float part = 0.f;
    #pragma unroll
    for (int u = 0; u < 8; u++) {
        int k = t + u * 1024;
        float p = ema_cs[k] * DECAY + ONE_MINUS_DECAY * g_counts[k];
        pre[u] = p;
        part += p;
    }
    #pragma unroll
    for (int o = 16; o; o >>= 1) part += __shfl_xor_sync(0xFFFFFFFFu, part, o);
    __shared__ float wsum[32];
    if ((t & 31) == 0) wsum[t >> 5] = part;
    __syncthreads();
    __shared__ float n_sh;
    if (t == 0) {
        float n = 0.f;
        for (int w = 0; w < 32; w++) n += wsum[w];
        n_sh = n;
    }
    __syncthreads();
    float n = n_sh;
    float denom = n + (float)KCODE * EPS;
    #pragma unroll
    for (int u = 0; u < 8; u++) {
        int k = t + u * 1024;
        float v = (pre[u] + EPS) / denom * n;
        out_cs[k] = v;
        g_newcs[k] = v;
    }
    if (t == 0) out_loss[0] = 0.25f * (float)(g_loss / (double)((size_t)NR * DIM));
}

// new_ema_w / new_embedding (dest at ODD float offsets -> scalar stores)
__global__ void k_ema(const float* __restrict__ ema_w,
                      float* __restrict__ out_w, float* __restrict__ out_emb) {
    int i = blockIdx.x * blockDim.x + threadIdx.x;
    int tot4 = KCODE * DIM / 4;
    if (i >= tot4) return;
    float4 w = ((const float4*)ema_w)[i];
    float4 dv = ((const float4*)g_dw)[i];
    float4 nw = make_float4(w.x * DECAY + ONE_MINUS_DECAY * dv.x,
                            w.y * DECAY + ONE_MINUS_DECAY * dv.y,
                            w.z * DECAY + ONE_MINUS_DECAY * dv.z,
                            w.w * DECAY + ONE_MINUS_DECAY * dv.w);
    float* pw = out_w + (size_t)i * 4;
    pw[0] = nw.x; pw[1] = nw.y; pw[2] = nw.z; pw[3] = nw.w;
    int k = i / (DIM / 4);
    float cs = fmaxf(g_newcs[k], EPS);
    float inv = 1.0f / cs;
    float* pe = out_emb + (size_t)i * 4;
    pe[0] = nw.x * inv; pe[1] = nw.y * inv; pe[2] = nw.z * inv; pe[3] = nw.w * inv;
}

// ---------------- launch ----------------
extern "C" void kernel_launch(void* const* d_in, const int* in_sizes, int n_in,
                              void* d_out, int out_size) {
    const float* inputs    = (const float*)d_in[0];
    const float* embedding = (const float*)d_in[1];
    const float* ema_cs    = (const float*)d_in[2];
    const float* ema_w     = (const float*)d_in[3];
    float* out = (float*)d_out;

    cudaFuncSetAttribute(k_argmax_mma, cudaFuncAttributeMaxDynamicSharedMemorySize, SMEM_SZ);

    k_zero<<<2048, 256>>>();
    k_norm<<<NR, 128>>>(inputs, 0);
    k_norm<<<KCODE, 128>>>(embedding, 1);
    k_argmax_mma<<<(NR / 128) * NSPLIT, 256, SMEM_SZ>>>();
    k_rescore_quant<<<NR, 128>>>(inputs, out, out + OFF_IDX);
    k_cs<<<1, 1024>>>(ema_cs, out + OFF_CS, out + OFF_LOSS);
    k_ema<<<(KCODE * DIM / 4 + 255) / 256, 256>>>(ema_w, out + OFF_W, out + OFF_EMB);
}

// round 17
// speedup vs baseline: 1.0480x; 1.0480x over previous
#include <cuda_runtime.h>
#include <cuda_bf16.h>
#include <math.h>

#define NR   32768
#define DIM  512
#define KCODE 8192
#define DECAY 0.99f
#define ONE_MINUS_DECAY 0.01f
#define EPS 1e-5f
#define MARGIN 3.0e-3f
#define MAXCAND 192

// ---------------- scratch (__device__ globals; no allocation) ----------------
static __device__ float  g_inv[NR];                            // per-row 1/||x||
static __device__ __align__(256) float  g_embn[KCODE * DIM];   // normalized embedding fp32
static __device__ __align__(256) __nv_bfloat16 g_flat_hi[NR * DIM];
static __device__ __align__(256) __nv_bfloat16 g_emb_hi[KCODE * DIM];
static __device__ int    g_clist[NR * MAXCAND];
static __device__ int    g_ccnt[NR];
static __device__ float  g_counts[KCODE];
static __device__ __align__(256) float  g_dw[KCODE * DIM];
static __device__ double g_loss;
static __device__ float  g_newcs[KCODE];

// ---------------- output layout (float32, concatenated in return order) -----
#define OFF_LOSS 16777216
#define OFF_IDX  16777217
#define OFF_CS   16809985
#define OFF_W    16818177
#define OFF_EMB  21012481

// ---------------- SMEM layout for argmax kernel ----------------
// A:    128 rows x 512 bf16 swizzled               [0, 131072)
// B:    3 ring bufs x (256 codes x 64 bf16)        [131072, 229376)
// PM:   128 rows x 4 warps fp32                    [229376, 231424)
// RMAX: 128 fp32                                   [231424, 231936)
#define S_A 0
#define S_B 131072
#define S_PM 229376
#define S_RMAX 231424
#define SMEM_SZ 231936

__device__ __forceinline__ unsigned smem_u32(const void* p) {
    unsigned a;
    asm("{ .reg .u64 t; cvta.to.shared.u64 t, %1; cvt.u32.u64 %0, t; }" : "=r"(a) : "l"(p));
    return a;
}
__device__ __forceinline__ void cp16(unsigned dst, const void* src) {
    asm volatile("cp.async.cg.shared.global [%0], [%1], 16;" :: "r"(dst), "l"(src));
}
#define CP_COMMIT() asm volatile("cp.async.commit_group;" ::: "memory")
#define CP_WAIT1()  asm volatile("cp.async.wait_group 1;" ::: "memory")

__device__ __forceinline__ void ldsm4(unsigned addr, unsigned& r0, unsigned& r1,
                                      unsigned& r2, unsigned& r3) {
    asm volatile("ldmatrix.sync.aligned.m8n8.x4.shared.b16 {%0,%1,%2,%3}, [%4];"
                 : "=r"(r0), "=r"(r1), "=r"(r2), "=r"(r3) : "r"(addr));
}
__device__ __forceinline__ void mma16816(float* d, const unsigned* a,
                                         unsigned b0, unsigned b1) {
    asm volatile("mma.sync.aligned.m16n8k16.row.col.f32.bf16.bf16.f32 "
                 "{%0,%1,%2,%3}, {%4,%5,%6,%7}, {%8,%9}, {%0,%1,%2,%3};"
                 : "+f"(d[0]), "+f"(d[1]), "+f"(d[2]), "+f"(d[3])
                 : "r"(a[0]), "r"(a[1]), "r"(a[2]), "r"(a[3]), "r"(b0), "r"(b1));
}

// swizzled byte offsets
__device__ __forceinline__ unsigned aoff(int row, int c) {   // A: 64 x 16B chunks/row
    return (unsigned)row * 1024u + (unsigned)((c & 56) | ((c ^ row) & 7)) * 16u;
}
__device__ __forceinline__ unsigned boff(int n, int cl) {    // B: 8 x 16B chunks/row
    return (unsigned)n * 128u + (unsigned)((cl ^ n) & 7) * 16u;
}

// ---------------- kernels ----------------
__global__ void k_zero() {
    int i = blockIdx.x * blockDim.x + threadIdx.x;
    int stride = gridDim.x * blockDim.x;
    float4 z = make_float4(0.f, 0.f, 0.f, 0.f);
    int tot4 = KCODE * DIM / 4;
    for (int j = i; j < tot4; j += stride) ((float4*)g_dw)[j] = z;
    for (int j = i; j < KCODE; j += stride) g_counts[j] = 0.f;
    for (int j = i; j < NR; j += stride) g_ccnt[j] = 0;
    if (i == 0) g_loss = 0.0;
}

// normalize rows; which==0: emit bf16-hi + inv-norm; which==1: emit fp32 + bf16-hi
__global__ void k_norm(const float* __restrict__ src, int which) {
    int row = blockIdx.x;
    int t = threadIdx.x;  // 128 threads, 4 floats each
    const float4* s = (const float4*)(src + (size_t)row * DIM);
    float4 v = s[t];
    float ss = v.x * v.x + v.y * v.y + v.z * v.z + v.w * v.w;
    #pragma unroll
    for (int o = 16; o; o >>= 1) ss += __shfl_xor_sync(0xFFFFFFFFu, ss, o);
    __shared__ float wsum[4];
    if ((t & 31) == 0) wsum[t >> 5] = ss;
    __syncthreads();
    float tot = wsum[0] + wsum[1] + wsum[2] + wsum[3];
    float inv = 1.0f / fmaxf(sqrtf(tot), 1e-12f);
    float4 o4 = make_float4(v.x * inv, v.y * inv, v.z * inv, v.w * inv);
    __nv_bfloat16* dhi = which ? g_emb_hi : g_flat_hi;
    if (which) {
        ((float4*)(g_embn + (size_t)row * DIM))[t] = o4;
    } else if (t == 0) {
        g_inv[row] = inv;
    }
    __nv_bfloat162 h0, h1;
    h0.x = __float2bfloat16(o4.x); h0.y = __float2bfloat16(o4.y);
    h1.x = __float2bfloat16(o4.z); h1.y = __float2bfloat16(o4.w);
    ((__nv_bfloat162*)(dhi + (size_t)row * DIM))[2 * t]     = h0;
    ((__nv_bfloat162*)(dhi + (size_t)row * DIM))[2 * t + 1] = h1;
}

// prefetch B tile tt (256 codes x 64 dims) into ring buffer tt%3
__device__ __forceinline__ void prefetchB(unsigned sb, int tid, int tt) {
    const int nn = tt >> 3, nk = tt & 7;
    unsigned bb = sb + S_B + (unsigned)(tt % 3) * 32768u;
    #pragma unroll
    for (int p = 0; p < 8; p++) {
        int g = p * 256 + tid;
        int n = g >> 3, cl = g & 7;
        cp16(bb + boff(n, cl),
             g_emb_hi + (size_t)(nn * 256 + n) * DIM + nk * 64 + cl * 8);
    }
}

// HMMA GEMM-argmax: 8 warps = 2m x 4n of 64x64 tiles, CTA chunk 128x256,
// 3-stage cp.async ring, ANTIPHASE ks order across warp parity (overlaps one
// warp's LDSM phase with the other's HMMA burst on each SMSP), margin cands.
__global__ __launch_bounds__(256, 1) void k_argmax_mma() {
    extern __shared__ __align__(16) char smem[];
    const unsigned sb = smem_u32(smem);
    float* pm   = (float*)(smem + S_PM);
    float* rmax = (float*)(smem + S_RMAX);
    const int tid = threadIdx.x;
    const int lane = tid & 31;
    const int wid = tid >> 5;
    const int r0 = blockIdx.x * 128;

    const int mw = wid & 1;              // m-half (64 rows)
    const int nw = wid >> 1;             // n-quarter (64 cols)
    const int rA0 = mw * 64 + (lane & 15);
    const int cc  = lane >> 4;           // 16B-chunk half for ldsm
    const int nB0 = nw * 64 + (lane & 15);
    const int kphase = (wid & 1) * 2;    // antiphase: odd warps do ks 2,3,0,1

    // ---- load resident A_hi (swizzled): 8192 chunks, 32/thread ----
    #pragma unroll 4
    for (int p = 0; p < 32; p++) {
        int g = p * 256 + tid;
        int row = g >> 6, c = g & 63;
        uint4 v = *(const uint4*)(g_flat_hi + (size_t)(r0 + row) * DIM + c * 8);
        *(uint4*)(smem + S_A + aoff(row, c)) = v;
    }
    if (tid < 128) rmax[tid] = -1e30f;

    float acc[4][8][4];
    #pragma unroll
    for (int mi = 0; mi < 4; mi++)
        #pragma unroll
        for (int nj = 0; nj < 8; nj++)
            #pragma unroll
            for (int q = 0; q < 4; q++) acc[mi][nj][q] = 0.f;

    // ---- prefetch tiles 0, 1 ----
    prefetchB(sb, tid, 0); CP_COMMIT();
    prefetchB(sb, tid, 1); CP_COMMIT();

    for (int t = 0; t < 256; t++) {
        CP_WAIT1();               // tile t arrived (this thread's copies)
        __syncthreads();          // tile t visible; buf (t+2)%3 free; A visible (t=0)
        if (t + 2 < 256) prefetchB(sb, tid, t + 2);
        CP_COMMIT();

        const unsigned Bb = sb + S_B + (unsigned)(t % 3) * 32768u;
        const int nk = t & 7;
        #pragma unroll
        for (int ksx = 0; ksx < 4; ksx++) {
            const int ks = (ksx + kphase) & 3;     // antiphase across warp parity
            const int cA = nk * 8 + ks * 2 + cc;
            unsigned a[4][4];
            #pragma unroll
            for (int mi = 0; mi < 4; mi++)
                ldsm4(sb + S_A + aoff(rA0 + mi * 16, cA),
                      a[mi][0], a[mi][1], a[mi][2], a[mi][3]);
            unsigned b[4][4];
            #pragma unroll
            for (int j = 0; j < 4; j++)
                ldsm4(Bb + boff(nB0 + j * 16, ks * 2 + cc),
                      b[j][0], b[j][1], b[j][2], b[j][3]);
            #pragma unroll
            for (int mi = 0; mi < 4; mi++)
                #pragma unroll
                for (int nj = 0; nj < 8; nj++) {
                    int jj = nj >> 1, s = nj & 1;
                    mma16816(acc[mi][nj], a[mi], b[jj][s], b[jj][s + 2]);
                }
        }

        if (nk == 7) {
            const int nc = t >> 3;
            // ---- register epilogue: per-row max over this warp's 64 cols ----
            float rm[8];
            #pragma unroll
            for (int mi = 0; mi < 4; mi++)
                #pragma unroll
                for (int h = 0; h < 2; h++) {
                    float m = -1e30f;
                    #pragma unroll
                    for (int nj = 0; nj < 8; nj++)
                        m = fmaxf(m, fmaxf(acc[mi][nj][h * 2], acc[mi][nj][h * 2 + 1]));
                    rm[mi * 2 + h] = m;
                }
            #pragma unroll
            for (int i = 0; i < 8; i++) {
                rm[i] = fmaxf(rm[i], __shfl_xor_sync(0xFFFFFFFFu, rm[i], 1));
                rm[i] = fmaxf(rm[i], __shfl_xor_sync(0xFFFFFFFFu, rm[i], 2));
            }
            if ((lane & 3) == 0) {
                #pragma unroll
                for (int mi = 0; mi < 4; mi++)
                    #pragma unroll
                    for (int h = 0; h < 2; h++) {
                        int row = mw * 64 + mi * 16 + h * 8 + (lane >> 2);
                        pm[row * 4 + nw] = rm[mi * 2 + h];
                    }
            }
            __syncthreads();
            if (tid < 128) {
                float4 v = *(float4*)&pm[tid * 4];
                float cm = fmaxf(fmaxf(v.x, v.y), fmaxf(v.z, v.w));
                float nm = fmaxf(rmax[tid], cm);
                rmax[tid] = nm;
                pm[tid * 4] = nm - MARGIN;     // threshold for this chunk
            }
            __syncthreads();
            // ---- candidate extraction (rare) ----
            #pragma unroll
            for (int mi = 0; mi < 4; mi++)
                #pragma unroll
                for (int h = 0; h < 2; h++) {
                    int row = mw * 64 + mi * 16 + h * 8 + (lane >> 2);
                    float th = pm[row * 4];
                    if (rm[mi * 2 + h] >= th) {
                        #pragma unroll
                        for (int nj = 0; nj < 8; nj++)
                            #pragma unroll
                            for (int q = 0; q < 2; q++) {
                                float v = acc[mi][nj][h * 2 + q];
                                if (v >= th) {
                                    int col = nc * 256 + nw * 64 + nj * 8 + (lane & 3) * 2 + q;
                                    int pos = atomicAdd(&g_ccnt[r0 + row], 1);
                                    if (pos < MAXCAND)
                                        g_clist[(size_t)(r0 + row) * MAXCAND + pos] = col;
                                }
                            }
                    }
                }
            // reset accumulators
            #pragma unroll
            for (int mi = 0; mi < 4; mi++)
                #pragma unroll
                for (int nj = 0; nj < 8; nj++)
                    #pragma unroll
                    for (int q = 0; q < 4; q++) acc[mi][nj][q] = 0.f;
        }
    }
}

// fused: exact fp32 rescore of candidates, then quantize/loss/counts/dw scatter.
// fv = xv*inv is bit-identical to the previously-stored g_flat values.
// Overflowed candidate list (never expected) -> exact full scan fallback.
__global__ void k_rescore_quant(const float* __restrict__ x,
                                float* __restrict__ qout,
                                float* __restrict__ idx_out) {
    int row = blockIdx.x;
    int t = threadIdx.x;  // 128
    int cnt = g_ccnt[row];
    bool full = (cnt > MAXCAND);
    int total = full ? KCODE : cnt;
    __shared__ float sred[4];
    __shared__ float bestd;
    __shared__ int   besti;
    if (t == 0) { bestd = 1e30f; besti = 0x7FFFFFFF; }
    __syncthreads();
    float4 xv = ((const float4*)(x + (size_t)row * DIM))[t];
    float inv = g_inv[row];
    float4 fv = make_float4(xv.x * inv, xv.y * inv, xv.z * inv, xv.w * inv);
    for (int c = 0; c < total; c++) {
        int idx = full ? c : g_clist[(size_t)row * MAXCAND + c];
        float4 e = ((const float4*)(g_embn + (size_t)idx * DIM))[t];
        float d = fv.x * e.x + fv.y * e.y + fv.z * e.z + fv.w * e.w;
        #pragma unroll
        for (int o = 16; o; o >>= 1) d += __shfl_xor_sync(0xFFFFFFFFu, d, o);
        if ((t & 31) == 0) sred[t >> 5] = d;
        __syncthreads();
        if (t == 0) {
            float dot = sred[0] + sred[1] + sred[2] + sred[3];
            float dist = 1.0f - dot;
            if (dist < bestd || (dist == bestd && idx < besti)) { bestd = dist; besti = idx; }
        }
        __syncthreads();
    }
    int idx = besti;
    if (t == 0) idx_out[row] = (float)idx;

    // ---- quant part ----
    float4 ev = ((const float4*)(g_embn + (size_t)idx * DIM))[t];
    float4 q; float d, s = 0.f;
    d = ev.x - xv.x; q.x = xv.x + d; s += d * d;
    d = ev.y - xv.y; q.y = xv.y + d; s += d * d;
    d = ev.z - xv.z; q.z = xv.z + d; s += d * d;
    d = ev.w - xv.w; q.w = xv.w + d; s += d * d;
    ((float4*)(qout + (size_t)row * DIM))[t] = q;

    float* dwp = g_dw + (size_t)idx * DIM + t * 4;
    atomicAdd(dwp + 0, fv.x);
    atomicAdd(dwp + 1, fv.y);
    atomicAdd(dwp + 2, fv.z);
    atomicAdd(dwp + 3, fv.w);

    #pragma unroll
    for (int o = 16; o; o >>= 1) s += __shfl_xor_sync(0xFFFFFFFFu, s, o);
    if ((t & 31) == 0) sred[t >> 5] = s;
    __syncthreads();
    if (t == 0) {
        atomicAdd(&g_loss, (double)(sred[0] + sred[1] + sred[2] + sred[3]));
        atomicAdd(&g_counts[idx], 1.0f);
    }
}

__global__ void k_cs(const float* __restrict__ ema_cs,
                     float* __restrict__ out_cs, float* __restrict__ out_loss) {
    int t = threadIdx.x;
    float pre[8];
    float part = 0.f;
    #pragma unroll
    for (int u = 0; u < 8; u++) {
        int k = t + u * 1024;
        float p = ema_cs[k] * DECAY + ONE_MINUS_DECAY * g_counts[k];
        pre[u] = p;
        part += p;
    }
    #pragma unroll
    for (int o = 16; o; o >>= 1) part += __shfl_xor_sync(0xFFFFFFFFu, part, o);
    __shared__ float wsum[32];
    if ((t & 31) == 0) wsum[t >> 5] = part;
    __syncthreads();
    __shared__ float n_sh;
    if (t == 0) {
        float n = 0.f;
        for (int w = 0; w < 32; w++) n += wsum[w];
        n_sh = n;
    }
    __syncthreads();
    float n = n_sh;
    float denom = n + (float)KCODE * EPS;
    #pragma unroll
    for (int u = 0; u < 8; u++) {
        int k = t + u * 1024;
        float v = (pre[u] + EPS) / denom * n;
        out_cs[k] = v;
        g_newcs[k] = v;
    }
    if (t == 0) out_loss[0] = 0.25f * (float)(g_loss / (double)((size_t)NR * DIM));
}

// new_ema_w / new_embedding (dest at ODD float offsets -> scalar stores)
__global__ void k_ema(const float* __restrict__ ema_w,
                      float* __restrict__ out_w, float* __restrict__ out_emb) {
    int i = blockIdx.x * blockDim.x + threadIdx.x;
    int tot4 = KCODE * DIM / 4;
    if (i >= tot4) return;
    float4 w = ((const float4*)ema_w)[i];
    float4 dv = ((const float4*)g_dw)[i];
    float4 nw = make_float4(w.x * DECAY + ONE_MINUS_DECAY * dv.x,
                            w.y * DECAY + ONE_MINUS_DECAY * dv.y,
                            w.z * DECAY + ONE_MINUS_DECAY * dv.z,
                            w.w * DECAY + ONE_MINUS_DECAY * dv.w);
    float* pw = out_w + (size_t)i * 4;
    pw[0] = nw.x; pw[1] = nw.y; pw[2] = nw.z; pw[3] = nw.w;
    int k = i / (DIM / 4);
    float cs = fmaxf(g_newcs[k], EPS);
    float inv = 1.0f / cs;
    float* pe = out_emb + (size_t)i * 4;
    pe[0] = nw.x * inv; pe[1] = nw.y * inv; pe[2] = nw.z * inv; pe[3] = nw.w * inv;
}

// ---------------- launch ----------------
extern "C" void kernel_launch(void* const* d_in, const int* in_sizes, int n_in,
                              void* d_out, int out_size) {
    const float* inputs    = (const float*)d_in[0];
    const float* embedding = (const float*)d_in[1];
    const float* ema_cs    = (const float*)d_in[2];
    const float* ema_w     = (const float*)d_in[3];
    float* out = (float*)d_out;

    cudaFuncSetAttribute(k_argmax_mma, cudaFuncAttributeMaxDynamicSharedMemorySize, SMEM_SZ);

    k_zero<<<2048, 256>>>();
    k_norm<<<NR, 128>>>(inputs, 0);
    k_norm<<<KCODE, 128>>>(embedding, 1);
    k_argmax_mma<<<NR / 128, 256, SMEM_SZ>>>();
    k_rescore_quant<<<NR, 128>>>(inputs, out, out + OFF_IDX);
    k_cs<<<1, 1024>>>(ema_cs, out + OFF_CS, out + OFF_LOSS);
    k_ema<<<(KCODE * DIM / 4 + 255) / 256, 256>>>(ema_w, out + OFF_W, out + OFF_EMB);
}